// round 16
// baseline (speedup 1.0000x reference)
#include <cuda_runtime.h>
#include <cuda_fp16.h>
#include <cstdint>

// Problem constants
#define B_  2
#define S_  2048
#define D_  1024
#define H_  16
#define DK_ 64
#define M_  (B_ * S_)   // 4096

// ---------------------------------------------------------------------------
// Scratch: hi parts for Q/C; hi+lo for K/V (attn B-side needs lo).
// ---------------------------------------------------------------------------
__device__ __half g_Qh[M_ * D_];
__device__ __half g_Kh[M_ * D_];
__device__ __half g_Kl[M_ * D_];
__device__ __half g_Vh[M_ * D_];
__device__ __half g_Vl[M_ * D_];
__device__ __half g_Ch[M_ * D_];

__device__ __forceinline__ uint32_t smem_u32(const void* p) {
    uint32_t a;
    asm("{ .reg .u64 t; cvta.to.shared.u64 t, %1; cvt.u32.u64 %0, t; }"
        : "=r"(a) : "l"(p));
    return a;
}

// fp16 MMA m16n8k16
__device__ __forceinline__ void mma16816(float* c,
                                         uint32_t a0, uint32_t a1, uint32_t a2, uint32_t a3,
                                         uint32_t b0, uint32_t b1) {
    asm volatile(
        "mma.sync.aligned.m16n8k16.row.col.f32.f16.f16.f32 "
        "{%0,%1,%2,%3}, {%4,%5,%6,%7}, {%8,%9}, {%0,%1,%2,%3};"
        : "+f"(c[0]), "+f"(c[1]), "+f"(c[2]), "+f"(c[3])
        : "r"(a0), "r"(a1), "r"(a2), "r"(a3), "r"(b0), "r"(b1));
}

__device__ __forceinline__ void ldsm4(uint32_t* r, uint32_t addr) {
    asm volatile("ldmatrix.sync.aligned.m8n8.x4.shared.b16 {%0,%1,%2,%3}, [%4];"
                 : "=r"(r[0]), "=r"(r[1]), "=r"(r[2]), "=r"(r[3]) : "r"(addr));
}

__device__ __forceinline__ void ldsm4t(uint32_t* r, uint32_t addr) {
    asm volatile("ldmatrix.sync.aligned.m8n8.x4.trans.shared.b16 {%0,%1,%2,%3}, [%4];"
                 : "=r"(r[0]), "=r"(r[1]), "=r"(r[2]), "=r"(r[3]) : "r"(addr));
}

union PackH4 { uint64_t u; __half b[4]; };

__device__ __forceinline__ void split4(float4 v, uint64_t& hi, uint64_t& lo) {
    PackH4 h, l;
    h.b[0] = __float2half_rn(v.x);
    h.b[1] = __float2half_rn(v.y);
    h.b[2] = __float2half_rn(v.z);
    h.b[3] = __float2half_rn(v.w);
    l.b[0] = __float2half_rn(v.x - __half2float(h.b[0]));
    l.b[1] = __float2half_rn(v.y - __half2float(h.b[1]));
    l.b[2] = __float2half_rn(v.z - __half2float(h.b[2]));
    l.b[3] = __float2half_rn(v.w - __half2float(h.b[3]));
    hi = h.u; lo = l.u;
}

__device__ __forceinline__ uint64_t hi4(float4 v) {
    PackH4 h;
    h.b[0] = __float2half_rn(v.x);
    h.b[1] = __float2half_rn(v.y);
    h.b[2] = __float2half_rn(v.z);
    h.b[3] = __float2half_rn(v.w);
    return h.u;
}

__device__ __forceinline__ uint32_t packh(float a, float b) {
    __half2 t = __halves2half2(__float2half_rn(a), __float2half_rn(b));
    return *(uint32_t*)&t;
}

// ===========================================================================
// 2-term split-fp16 GEMM+bias: Y ~= Ah*Bh + Ah*Bl  (A-side lo dropped).
// MODE 0: fp32 X in (convert hi only), fp16 hi/lo out (QKV projections)
// MODE 1: fp16 Ah in, fp32 out (final projection)
// ===========================================================================
#define BM 128
#define BN 128
#define BK 32

template<int MODE>
__global__ __launch_bounds__(256, 2) void gemm_mma_kernel(
    const float* __restrict__ X0, const float* __restrict__ X1, const float* __restrict__ X2,
    const __half* __restrict__ Ahg,
    const float* __restrict__ W0, const float* __restrict__ W1, const float* __restrict__ W2,
    const float* __restrict__ bias0, const float* __restrict__ bias1, const float* __restrict__ bias2,
    float* __restrict__ Yf,
    __half* __restrict__ Yh0, __half* __restrict__ Yh1, __half* __restrict__ Yh2,
    __half* __restrict__ Yl0, __half* __restrict__ Yl1, __half* __restrict__ Yl2)
{
    __shared__ __align__(128) __half sAh[BM * 40];
    __shared__ __align__(128) __half sBh[BN * 40];
    __shared__ __align__(128) __half sBl[BN * 40];

    const int tid  = threadIdx.x;
    const int lane = tid & 31;
    const int wid  = tid >> 5;
    const int wm   = wid >> 2;
    const int wn   = wid & 3;
    const int m0 = blockIdx.y * BM;
    const int n0 = blockIdx.x * BN;
    const int z  = blockIdx.z;

    const float* X = (z == 0) ? X0 : (z == 1) ? X1 : X2;
    const float* W = (z == 0) ? W0 : (z == 1) ? W1 : W2;
    const float* bias = (z == 0) ? bias0 : (z == 1) ? bias1 : bias2;
    __half* Yh = (z == 0) ? Yh0 : (z == 1) ? Yh1 : Yh2;
    __half* Yl = (z == 0) ? Yl0 : (z == 1) ? Yl1 : Yl2;

    const uint32_t bAh = smem_u32(sAh);
    const uint32_t bBh = smem_u32(sBh);
    const uint32_t bBl = smem_u32(sBl);

    const uint32_t aoff = (uint32_t)((lane & 15) * 80 + (lane >> 4) * 16);
    const uint32_t boff = (uint32_t)(((lane & 7) + ((lane >> 4) & 1) * 8) * 80 +
                                     (((lane >> 3) & 1) ? 16 : 0));

    const int lr = tid >> 3;
    const int lc = tid & 7;

    float C[4][4][4];
#pragma unroll
    for (int i = 0; i < 4; i++)
#pragma unroll
        for (int j = 0; j < 4; j++)
#pragma unroll
            for (int t = 0; t < 4; t++) C[i][j][t] = 0.0f;

    for (int k0 = 0; k0 < D_; k0 += BK) {
        __syncthreads();
        if (MODE == 0) {
#pragma unroll
            for (int it = 0; it < 4; it++) {
                const int r = lr + it * 32;
                float4 xv = *(const float4*)&X[(size_t)(m0 + r) * D_ + k0 + lc * 4];
                *(uint64_t*)((char*)sAh + r * 80 + lc * 8) = hi4(xv);
            }
        } else {
#pragma unroll
            for (int i = 0; i < 2; i++) {
                const int idx = tid + i * 256;
                const int rr = idx >> 2;
                const int cc = idx & 3;
                const size_t g = (size_t)(m0 + rr) * D_ + k0 + cc * 8;
                *(uint4*)((char*)sAh + rr * 80 + cc * 16) = *(const uint4*)&Ahg[g];
            }
        }
#pragma unroll
        for (int it = 0; it < 4; it++) {
            const int r = lr + it * 32;
            uint64_t hi, lo;
            float4 wv = *(const float4*)&W[(size_t)(n0 + r) * D_ + k0 + lc * 4];
            split4(wv, hi, lo);
            *(uint64_t*)((char*)sBh + r * 80 + lc * 8) = hi;
            *(uint64_t*)((char*)sBl + r * 80 + lc * 8) = lo;
        }
        __syncthreads();

#pragma unroll
        for (int ks = 0; ks < 2; ks++) {
            const uint32_t kbyte = (uint32_t)(ks * 32);
            uint32_t bh[2][4], bl[2][4];
#pragma unroll
            for (int p = 0; p < 2; p++) {
                ldsm4(bh[p], bBh + (uint32_t)((wn * 32 + p * 16) * 80) + kbyte + boff);
                ldsm4(bl[p], bBl + (uint32_t)((wn * 32 + p * 16) * 80) + kbyte + boff);
            }
            uint32_t a[4][4];
#pragma unroll
            for (int i = 0; i < 4; i++)
                ldsm4(a[i], bAh + (uint32_t)((wm * 64 + i * 16) * 80) + kbyte + aoff);
            // pass 1: Ah*Bh
#pragma unroll
            for (int i = 0; i < 4; i++)
#pragma unroll
                for (int j = 0; j < 4; j++)
                    mma16816(C[i][j], a[i][0], a[i][1], a[i][2], a[i][3],
                             bh[j >> 1][(j & 1) * 2], bh[j >> 1][(j & 1) * 2 + 1]);
            // pass 2: Ah*Bl
#pragma unroll
            for (int i = 0; i < 4; i++)
#pragma unroll
                for (int j = 0; j < 4; j++)
                    mma16816(C[i][j], a[i][0], a[i][1], a[i][2], a[i][3],
                             bl[j >> 1][(j & 1) * 2], bl[j >> 1][(j & 1) * 2 + 1]);
        }
    }

    const int qr = lane >> 2;
    const int qc = (lane & 3) * 2;
#pragma unroll
    for (int i = 0; i < 4; i++) {
        const int row0 = m0 + wm * 64 + i * 16 + qr;
#pragma unroll
        for (int j = 0; j < 4; j++) {
            const int col = n0 + wn * 32 + j * 8 + qc;
            const float b0v = bias[col], b1v = bias[col + 1];
            float v0 = C[i][j][0] + b0v, v1 = C[i][j][1] + b1v;
            float v2 = C[i][j][2] + b0v, v3 = C[i][j][3] + b1v;
            if (MODE == 0) {
                __half h0 = __float2half_rn(v0);
                __half h1 = __float2half_rn(v1);
                __half h2 = __float2half_rn(v2);
                __half h3 = __float2half_rn(v3);
                __half2 hp0 = __halves2half2(h0, h1);
                __half2 hp1 = __halves2half2(h2, h3);
                *(uint32_t*)&Yh[(size_t)row0 * D_ + col]       = *(uint32_t*)&hp0;
                *(uint32_t*)&Yh[(size_t)(row0 + 8) * D_ + col] = *(uint32_t*)&hp1;
                if (Yl) {
                    *(uint32_t*)&Yl[(size_t)row0 * D_ + col] =
                        packh(v0 - __half2float(h0), v1 - __half2float(h1));
                    *(uint32_t*)&Yl[(size_t)(row0 + 8) * D_ + col] =
                        packh(v2 - __half2float(h2), v3 - __half2float(h3));
                }
            } else {
                float2 o0 = { v0, v1 };
                float2 o1 = { v2, v3 };
                *(float2*)&Yf[(size_t)row0 * D_ + col]       = o0;
                *(float2*)&Yf[(size_t)(row0 + 8) * D_ + col] = o1;
            }
        }
    }
}

// ===========================================================================
// Flash attention — R15 body (2-term QK and PV); context written hi-only.
// ===========================================================================
#define ATQ 128
#define ATK 64
#define ALD 144

#define AOFF_QH 0
#define AOFF_KH (ATQ * ALD)
#define AOFF_KL (AOFF_KH + ATK * ALD)
#define AOFF_VH (AOFF_KL + ATK * ALD)
#define AOFF_VL (AOFF_VH + ATK * ALD)
#define ATTN_SMEM_BYTES (AOFF_VL + ATK * ALD)  // 55296

__global__ __launch_bounds__(256) void attn_mma_kernel(
    const __half* __restrict__ Qh,
    const __half* __restrict__ Kh, const __half* __restrict__ Kl,
    const __half* __restrict__ Vh, const __half* __restrict__ Vl,
    const int* __restrict__ mask,
    __half* __restrict__ Ch)
{
    extern __shared__ __align__(128) char smem[];
    const uint32_t sb = smem_u32(smem);

    const int tid  = threadIdx.x;
    const int lane = tid & 31;
    const int wid  = tid >> 5;
    const int bh = blockIdx.y;
    const int b  = bh >> 4;
    const int h  = bh & 15;
    const int q0 = blockIdx.x * ATQ;

    const size_t base = (size_t)b * S_ * D_ + (size_t)h * DK_;
    const __half* Qhb = Qh + base;
    const __half* Khb = Kh + base;
    const __half* Klb = Kl + base;
    const __half* Vhb = Vh + base;
    const __half* Vlb = Vl + base;
    const int* Mb = mask + (size_t)b * S_ * S_;

    // ---- load Q hi tile ----
#pragma unroll
    for (int i = 0; i < 4; i++) {
        const int idx = tid + i * 256;
        const int rr = idx >> 3;
        const int cc = idx & 7;
        *(uint4*)(smem + AOFF_QH + rr * ALD + cc * 16) =
            *(const uint4*)&Qhb[(size_t)(q0 + rr) * D_ + cc * 8];
    }

    const uint32_t aoffQ = sb + (uint32_t)((wid * 16 + (lane & 15)) * ALD + (lane >> 4) * 16);
    const uint32_t boffK = sb + (uint32_t)(((lane & 7) + ((lane >> 4) & 1) * 8) * ALD +
                                           ((lane >> 3) & 1) * 16);
    const uint32_t voffV = sb + (uint32_t)((((lane >> 3) & 1) * 8 + (lane & 7)) * ALD +
                                           ((lane >> 4) & 1) * 16);

    float mstate[2] = { -1e30f, -1e30f };
    float lstate[2] = { 0.0f, 0.0f };
    float O[8][4];
#pragma unroll
    for (int j = 0; j < 8; j++)
#pragma unroll
        for (int t = 0; t < 4; t++) O[j][t] = 0.0f;

    const int row0 = q0 + wid * 16 + (lane >> 2);
    const int mcol = (lane & 3) * 2;
    const int* mrow0 = Mb + (size_t)row0 * S_;
    const int* mrow1 = Mb + (size_t)(row0 + 8) * S_;

    for (int k0 = 0; k0 < S_; k0 += ATK) {
        __syncthreads();
#pragma unroll
        for (int i = 0; i < 2; i++) {
            const int idx = tid + i * 256;
            const int rr = idx >> 3;
            const int cc = idx & 7;
            const size_t g = (size_t)(k0 + rr) * D_ + cc * 8;
            *(uint4*)(smem + AOFF_KH + rr * ALD + cc * 16) = *(const uint4*)&Khb[g];
            *(uint4*)(smem + AOFF_KL + rr * ALD + cc * 16) = *(const uint4*)&Klb[g];
            *(uint4*)(smem + AOFF_VH + rr * ALD + cc * 16) = *(const uint4*)&Vhb[g];
            *(uint4*)(smem + AOFF_VL + rr * ALD + cc * 16) = *(const uint4*)&Vlb[g];
        }
        __syncthreads();

        // ---- S = Q K^T (2-term) ----
        float Sf[8][4];
#pragma unroll
        for (int j = 0; j < 8; j++)
#pragma unroll
            for (int tt = 0; tt < 4; tt++) Sf[j][tt] = 0.0f;

#pragma unroll
        for (int kc = 0; kc < 4; kc++) {
            const uint32_t kb = (uint32_t)(kc * 32);
            uint32_t ah[4];
            ldsm4(ah, aoffQ + AOFF_QH + kb);
#pragma unroll
            for (int jp = 0; jp < 4; jp++) {
                uint32_t kh[4], kl[4];
                ldsm4(kh, boffK + AOFF_KH + (uint32_t)(jp * 16 * ALD) + kb);
                ldsm4(kl, boffK + AOFF_KL + (uint32_t)(jp * 16 * ALD) + kb);
                mma16816(Sf[jp * 2],     ah[0], ah[1], ah[2], ah[3], kh[0], kh[1]);
                mma16816(Sf[jp * 2],     ah[0], ah[1], ah[2], ah[3], kl[0], kl[1]);
                mma16816(Sf[jp * 2 + 1], ah[0], ah[1], ah[2], ah[3], kh[2], kh[3]);
                mma16816(Sf[jp * 2 + 1], ah[0], ah[1], ah[2], ah[3], kl[2], kl[3]);
            }
        }

        // ---- scale + mask ----
#pragma unroll
        for (int j = 0; j < 8; j++) {
            int2 mv0 = *(const int2*)&mrow0[k0 + j * 8 + mcol];
            int2 mv1 = *(const int2*)&mrow1[k0 + j * 8 + mcol];
            Sf[j][0] = (mv0.x == 0) ? -1e9f : Sf[j][0] * 0.125f;
            Sf[j][1] = (mv0.y == 0) ? -1e9f : Sf[j][1] * 0.125f;
            Sf[j][2] = (mv1.x == 0) ? -1e9f : Sf[j][2] * 0.125f;
            Sf[j][3] = (mv1.y == 0) ? -1e9f : Sf[j][3] * 0.125f;
        }

        // ---- online softmax ----
        float corr[2];
#pragma unroll
        for (int rr = 0; rr < 2; rr++) {
            float mx = -1e30f;
#pragma unroll
            for (int j = 0; j < 8; j++)
                mx = fmaxf(mx, fmaxf(Sf[j][rr * 2], Sf[j][rr * 2 + 1]));
            mx = fmaxf(mx, __shfl_xor_sync(0xFFFFFFFF, mx, 1));
            mx = fmaxf(mx, __shfl_xor_sync(0xFFFFFFFF, mx, 2));
            float mnew = fmaxf(mstate[rr], mx);
            corr[rr] = __expf(mstate[rr] - mnew);
            float sum = 0.0f;
#pragma unroll
            for (int j = 0; j < 8; j++) {
                float p0 = __expf(Sf[j][rr * 2]     - mnew);
                float p1 = __expf(Sf[j][rr * 2 + 1] - mnew);
                Sf[j][rr * 2] = p0; Sf[j][rr * 2 + 1] = p1;
                sum += p0 + p1;
            }
            sum += __shfl_xor_sync(0xFFFFFFFF, sum, 1);
            sum += __shfl_xor_sync(0xFFFFFFFF, sum, 2);
            lstate[rr] = lstate[rr] * corr[rr] + sum;
            mstate[rr] = mnew;
        }

#pragma unroll
        for (int j = 0; j < 8; j++) {
            O[j][0] *= corr[0]; O[j][1] *= corr[0];
            O[j][2] *= corr[1]; O[j][3] *= corr[1];
        }

        // ---- pack P hi ----
        uint32_t aPh[4][4];
#pragma unroll
        for (int kc = 0; kc < 4; kc++) {
#pragma unroll
            for (int half = 0; half < 2; half++) {
                const int j = kc * 2 + half;
#pragma unroll
                for (int rr = 0; rr < 2; rr++) {
                    __half2 hp = __halves2half2(__float2half_rn(Sf[j][rr * 2]),
                                                __float2half_rn(Sf[j][rr * 2 + 1]));
                    aPh[kc][half * 2 + rr] = *(uint32_t*)&hp;
                }
            }
        }

        // ---- O += P V (2-term) ----
#pragma unroll
        for (int kc = 0; kc < 4; kc++) {
#pragma unroll
            for (int jp = 0; jp < 4; jp++) {
                uint32_t vh[4], vl[4];
                ldsm4t(vh, voffV + AOFF_VH + (uint32_t)(kc * 16 * ALD) + (uint32_t)(jp * 32));
                ldsm4t(vl, voffV + AOFF_VL + (uint32_t)(kc * 16 * ALD) + (uint32_t)(jp * 32));
                mma16816(O[jp * 2],     aPh[kc][0], aPh[kc][1], aPh[kc][2], aPh[kc][3], vh[0], vh[1]);
                mma16816(O[jp * 2],     aPh[kc][0], aPh[kc][1], aPh[kc][2], aPh[kc][3], vl[0], vl[1]);
                mma16816(O[jp * 2 + 1], aPh[kc][0], aPh[kc][1], aPh[kc][2], aPh[kc][3], vh[2], vh[3]);
                mma16816(O[jp * 2 + 1], aPh[kc][0], aPh[kc][1], aPh[kc][2], aPh[kc][3], vl[2], vl[3]);
            }
        }
        __syncthreads();
    }

    // ---- finalize: write context hi only ----
    const float inv0 = 1.0f / lstate[0];
    const float inv1 = 1.0f / lstate[1];
    __half* Chb = Ch + base;
#pragma unroll
    for (int j = 0; j < 8; j++) {
        const int col = j * 8 + mcol;
        *(uint32_t*)&Chb[(size_t)row0 * D_ + col] =
            packh(O[j][0] * inv0, O[j][1] * inv0);
        *(uint32_t*)&Chb[(size_t)(row0 + 8) * D_ + col] =
            packh(O[j][2] * inv1, O[j][3] * inv1);
    }
}

// ---------------------------------------------------------------------------
// Launch
// ---------------------------------------------------------------------------
extern "C" void kernel_launch(void* const* d_in, const int* in_sizes, int n_in,
                              void* d_out, int out_size)
{
    (void)in_sizes; (void)n_in; (void)out_size;
    const float* q    = (const float*)d_in[0];
    const float* k    = (const float*)d_in[1];
    const float* v    = (const float*)d_in[2];
    const int*   mask = (const int*)d_in[3];
    const float* w_q  = (const float*)d_in[4];
    const float* b_q  = (const float*)d_in[5];
    const float* w_k  = (const float*)d_in[6];
    const float* b_k  = (const float*)d_in[7];
    const float* w_v  = (const float*)d_in[8];
    const float* b_v  = (const float*)d_in[9];
    const float* w_o  = (const float*)d_in[10];
    const float* b_o  = (const float*)d_in[11];
    float* out = (float*)d_out;

    __half *gQh, *gKh, *gKl, *gVh, *gVl, *gCh;
    cudaGetSymbolAddress((void**)&gQh, g_Qh);
    cudaGetSymbolAddress((void**)&gKh, g_Kh);
    cudaGetSymbolAddress((void**)&gKl, g_Kl);
    cudaGetSymbolAddress((void**)&gVh, g_Vh);
    cudaGetSymbolAddress((void**)&gVl, g_Vl);
    cudaGetSymbolAddress((void**)&gCh, g_Ch);

    cudaFuncSetAttribute(attn_mma_kernel,
                         cudaFuncAttributeMaxDynamicSharedMemorySize,
                         ATTN_SMEM_BYTES);

    dim3 gblk(256);

    // Q/K/V projections (2-term). Q needs hi only (Yl = nullptr -> skip lo writes).
    dim3 ggrid3(D_ / BN, M_ / BM, 3);
    gemm_mma_kernel<0><<<ggrid3, gblk>>>(
        q, k, v, nullptr,
        w_q, w_k, w_v, b_q, b_k, b_v,
        nullptr,
        gQh, gKh, gVh, nullptr, gKl, gVl);

    dim3 ablk(256);
    dim3 agrid(S_ / ATQ, B_ * H_);    // (16, 32)
    attn_mma_kernel<<<agrid, ablk, ATTN_SMEM_BYTES>>>(
        gQh, gKh, gKl, gVh, gVl, mask, gCh);

    // final projection (2-term, A = Ch)
    dim3 ggrid1(D_ / BN, M_ / BM, 1);
    gemm_mma_kernel<1><<<ggrid1, gblk>>>(
        nullptr, nullptr, nullptr, gCh,
        w_o, nullptr, nullptr, b_o, nullptr, nullptr,
        out,
        nullptr, nullptr, nullptr, nullptr, nullptr, nullptr);
}

// round 17
// speedup vs baseline: 1.5024x; 1.5024x over previous
#include <cuda_runtime.h>
#include <cuda_fp16.h>
#include <cstdint>

// Problem constants
#define B_  2
#define S_  2048
#define D_  1024
#define H_  16
#define DK_ 64
#define M_  (B_ * S_)   // 4096

// ---------------------------------------------------------------------------
// Scratch: hi parts for Q/C; hi+lo for K/V (attn B-side needs lo).
// ---------------------------------------------------------------------------
__device__ __half g_Qh[M_ * D_];
__device__ __half g_Kh[M_ * D_];
__device__ __half g_Kl[M_ * D_];
__device__ __half g_Vh[M_ * D_];
__device__ __half g_Vl[M_ * D_];
__device__ __half g_Ch[M_ * D_];

__device__ __forceinline__ uint32_t smem_u32(const void* p) {
    uint32_t a;
    asm("{ .reg .u64 t; cvta.to.shared.u64 t, %1; cvt.u32.u64 %0, t; }"
        : "=r"(a) : "l"(p));
    return a;
}

// fp16 MMA m16n8k16
__device__ __forceinline__ void mma16816(float* c,
                                         uint32_t a0, uint32_t a1, uint32_t a2, uint32_t a3,
                                         uint32_t b0, uint32_t b1) {
    asm volatile(
        "mma.sync.aligned.m16n8k16.row.col.f32.f16.f16.f32 "
        "{%0,%1,%2,%3}, {%4,%5,%6,%7}, {%8,%9}, {%0,%1,%2,%3};"
        : "+f"(c[0]), "+f"(c[1]), "+f"(c[2]), "+f"(c[3])
        : "r"(a0), "r"(a1), "r"(a2), "r"(a3), "r"(b0), "r"(b1));
}

__device__ __forceinline__ void ldsm4(uint32_t* r, uint32_t addr) {
    asm volatile("ldmatrix.sync.aligned.m8n8.x4.shared.b16 {%0,%1,%2,%3}, [%4];"
                 : "=r"(r[0]), "=r"(r[1]), "=r"(r[2]), "=r"(r[3]) : "r"(addr));
}

__device__ __forceinline__ void ldsm4t(uint32_t* r, uint32_t addr) {
    asm volatile("ldmatrix.sync.aligned.m8n8.x4.trans.shared.b16 {%0,%1,%2,%3}, [%4];"
                 : "=r"(r[0]), "=r"(r[1]), "=r"(r[2]), "=r"(r[3]) : "r"(addr));
}

union PackH4 { uint64_t u; __half b[4]; };

__device__ __forceinline__ void split4(float4 v, uint64_t& hi, uint64_t& lo) {
    PackH4 h, l;
    h.b[0] = __float2half_rn(v.x);
    h.b[1] = __float2half_rn(v.y);
    h.b[2] = __float2half_rn(v.z);
    h.b[3] = __float2half_rn(v.w);
    l.b[0] = __float2half_rn(v.x - __half2float(h.b[0]));
    l.b[1] = __float2half_rn(v.y - __half2float(h.b[1]));
    l.b[2] = __float2half_rn(v.z - __half2float(h.b[2]));
    l.b[3] = __float2half_rn(v.w - __half2float(h.b[3]));
    hi = h.u; lo = l.u;
}

__device__ __forceinline__ uint64_t hi4(float4 v) {
    PackH4 h;
    h.b[0] = __float2half_rn(v.x);
    h.b[1] = __float2half_rn(v.y);
    h.b[2] = __float2half_rn(v.z);
    h.b[3] = __float2half_rn(v.w);
    return h.u;
}

__device__ __forceinline__ uint32_t packh(float a, float b) {
    __half2 t = __halves2half2(__float2half_rn(a), __float2half_rn(b));
    return *(uint32_t*)&t;
}

// ===========================================================================
// 2-term split-fp16 GEMM+bias: Y ~= Ah*Bh + Ah*Bl  (A-side lo dropped).
// MODE 0: fp32 X in (convert hi only), fp16 hi/lo out (QKV projections)
// MODE 1: fp16 Ah in, fp32 out (final projection)
// ===========================================================================
#define BM 128
#define BN 128
#define BK 32

template<int MODE>
__global__ __launch_bounds__(256, 2) void gemm_mma_kernel(
    const float* __restrict__ X0, const float* __restrict__ X1, const float* __restrict__ X2,
    const __half* __restrict__ Ahg,
    const float* __restrict__ W0, const float* __restrict__ W1, const float* __restrict__ W2,
    const float* __restrict__ bias0, const float* __restrict__ bias1, const float* __restrict__ bias2,
    float* __restrict__ Yf,
    __half* __restrict__ Yh0, __half* __restrict__ Yh1, __half* __restrict__ Yh2,
    __half* __restrict__ Yl0, __half* __restrict__ Yl1, __half* __restrict__ Yl2)
{
    __shared__ __align__(128) __half sAh[BM * 40];
    __shared__ __align__(128) __half sBh[BN * 40];
    __shared__ __align__(128) __half sBl[BN * 40];

    const int tid  = threadIdx.x;
    const int lane = tid & 31;
    const int wid  = tid >> 5;
    const int wm   = wid >> 2;
    const int wn   = wid & 3;
    const int m0 = blockIdx.y * BM;
    const int n0 = blockIdx.x * BN;
    const int z  = blockIdx.z;

    const float* X = (z == 0) ? X0 : (z == 1) ? X1 : X2;
    const float* W = (z == 0) ? W0 : (z == 1) ? W1 : W2;
    const float* bias = (z == 0) ? bias0 : (z == 1) ? bias1 : bias2;
    __half* Yh = (z == 0) ? Yh0 : (z == 1) ? Yh1 : Yh2;
    __half* Yl = (z == 0) ? Yl0 : (z == 1) ? Yl1 : Yl2;

    const uint32_t bAh = smem_u32(sAh);
    const uint32_t bBh = smem_u32(sBh);
    const uint32_t bBl = smem_u32(sBl);

    const uint32_t aoff = (uint32_t)((lane & 15) * 80 + (lane >> 4) * 16);
    const uint32_t boff = (uint32_t)(((lane & 7) + ((lane >> 4) & 1) * 8) * 80 +
                                     (((lane >> 3) & 1) ? 16 : 0));

    const int lr = tid >> 3;
    const int lc = tid & 7;

    float C[4][4][4];
#pragma unroll
    for (int i = 0; i < 4; i++)
#pragma unroll
        for (int j = 0; j < 4; j++)
#pragma unroll
            for (int t = 0; t < 4; t++) C[i][j][t] = 0.0f;

    for (int k0 = 0; k0 < D_; k0 += BK) {
        __syncthreads();
        if (MODE == 0) {
#pragma unroll
            for (int it = 0; it < 4; it++) {
                const int r = lr + it * 32;
                float4 xv = *(const float4*)&X[(size_t)(m0 + r) * D_ + k0 + lc * 4];
                *(uint64_t*)((char*)sAh + r * 80 + lc * 8) = hi4(xv);
            }
        } else {
#pragma unroll
            for (int i = 0; i < 2; i++) {
                const int idx = tid + i * 256;
                const int rr = idx >> 2;
                const int cc = idx & 3;
                const size_t g = (size_t)(m0 + rr) * D_ + k0 + cc * 8;
                *(uint4*)((char*)sAh + rr * 80 + cc * 16) = *(const uint4*)&Ahg[g];
            }
        }
#pragma unroll
        for (int it = 0; it < 4; it++) {
            const int r = lr + it * 32;
            uint64_t hi, lo;
            float4 wv = *(const float4*)&W[(size_t)(n0 + r) * D_ + k0 + lc * 4];
            split4(wv, hi, lo);
            *(uint64_t*)((char*)sBh + r * 80 + lc * 8) = hi;
            *(uint64_t*)((char*)sBl + r * 80 + lc * 8) = lo;
        }
        __syncthreads();

#pragma unroll
        for (int ks = 0; ks < 2; ks++) {
            const uint32_t kbyte = (uint32_t)(ks * 32);
            uint32_t bh[2][4], bl[2][4];
#pragma unroll
            for (int p = 0; p < 2; p++) {
                ldsm4(bh[p], bBh + (uint32_t)((wn * 32 + p * 16) * 80) + kbyte + boff);
                ldsm4(bl[p], bBl + (uint32_t)((wn * 32 + p * 16) * 80) + kbyte + boff);
            }
            uint32_t a[4][4];
#pragma unroll
            for (int i = 0; i < 4; i++)
                ldsm4(a[i], bAh + (uint32_t)((wm * 64 + i * 16) * 80) + kbyte + aoff);
            // pass 1: Ah*Bh
#pragma unroll
            for (int i = 0; i < 4; i++)
#pragma unroll
                for (int j = 0; j < 4; j++)
                    mma16816(C[i][j], a[i][0], a[i][1], a[i][2], a[i][3],
                             bh[j >> 1][(j & 1) * 2], bh[j >> 1][(j & 1) * 2 + 1]);
            // pass 2: Ah*Bl
#pragma unroll
            for (int i = 0; i < 4; i++)
#pragma unroll
                for (int j = 0; j < 4; j++)
                    mma16816(C[i][j], a[i][0], a[i][1], a[i][2], a[i][3],
                             bl[j >> 1][(j & 1) * 2], bl[j >> 1][(j & 1) * 2 + 1]);
        }
    }

    const int qr = lane >> 2;
    const int qc = (lane & 3) * 2;
#pragma unroll
    for (int i = 0; i < 4; i++) {
        const int row0 = m0 + wm * 64 + i * 16 + qr;
#pragma unroll
        for (int j = 0; j < 4; j++) {
            const int col = n0 + wn * 32 + j * 8 + qc;
            const float b0v = bias[col], b1v = bias[col + 1];
            float v0 = C[i][j][0] + b0v, v1 = C[i][j][1] + b1v;
            float v2 = C[i][j][2] + b0v, v3 = C[i][j][3] + b1v;
            if (MODE == 0) {
                __half h0 = __float2half_rn(v0);
                __half h1 = __float2half_rn(v1);
                __half h2 = __float2half_rn(v2);
                __half h3 = __float2half_rn(v3);
                __half2 hp0 = __halves2half2(h0, h1);
                __half2 hp1 = __halves2half2(h2, h3);
                *(uint32_t*)&Yh[(size_t)row0 * D_ + col]       = *(uint32_t*)&hp0;
                *(uint32_t*)&Yh[(size_t)(row0 + 8) * D_ + col] = *(uint32_t*)&hp1;
                if (Yl) {
                    *(uint32_t*)&Yl[(size_t)row0 * D_ + col] =
                        packh(v0 - __half2float(h0), v1 - __half2float(h1));
                    *(uint32_t*)&Yl[(size_t)(row0 + 8) * D_ + col] =
                        packh(v2 - __half2float(h2), v3 - __half2float(h3));
                }
            } else {
                float2 o0 = { v0, v1 };
                float2 o1 = { v2, v3 };
                *(float2*)&Yf[(size_t)row0 * D_ + col]       = o0;
                *(float2*)&Yf[(size_t)(row0 + 8) * D_ + col] = o1;
            }
        }
    }
}

// ===========================================================================
// Flash attention — 2-term QK and PV; context written hi-only.
// ===========================================================================
#define ATQ 128
#define ATK 64
#define ALD 144

#define AOFF_QH 0
#define AOFF_KH (ATQ * ALD)
#define AOFF_KL (AOFF_KH + ATK * ALD)
#define AOFF_VH (AOFF_KL + ATK * ALD)
#define AOFF_VL (AOFF_VH + ATK * ALD)
#define ATTN_SMEM_BYTES (AOFF_VL + ATK * ALD)  // 55296

__global__ __launch_bounds__(256) void attn_mma_kernel(
    const __half* __restrict__ Qh,
    const __half* __restrict__ Kh, const __half* __restrict__ Kl,
    const __half* __restrict__ Vh, const __half* __restrict__ Vl,
    const int* __restrict__ mask,
    __half* __restrict__ Ch)
{
    extern __shared__ __align__(128) char smem[];
    const uint32_t sb = smem_u32(smem);

    const int tid  = threadIdx.x;
    const int lane = tid & 31;
    const int wid  = tid >> 5;
    const int bh = blockIdx.y;
    const int b  = bh >> 4;
    const int h  = bh & 15;
    const int q0 = blockIdx.x * ATQ;

    const size_t base = (size_t)b * S_ * D_ + (size_t)h * DK_;
    const __half* Qhb = Qh + base;
    const __half* Khb = Kh + base;
    const __half* Klb = Kl + base;
    const __half* Vhb = Vh + base;
    const __half* Vlb = Vl + base;
    const int* Mb = mask + (size_t)b * S_ * S_;

    // ---- load Q hi tile ----
#pragma unroll
    for (int i = 0; i < 4; i++) {
        const int idx = tid + i * 256;
        const int rr = idx >> 3;
        const int cc = idx & 7;
        *(uint4*)(smem + AOFF_QH + rr * ALD + cc * 16) =
            *(const uint4*)&Qhb[(size_t)(q0 + rr) * D_ + cc * 8];
    }

    const uint32_t aoffQ = sb + (uint32_t)((wid * 16 + (lane & 15)) * ALD + (lane >> 4) * 16);
    const uint32_t boffK = sb + (uint32_t)(((lane & 7) + ((lane >> 4) & 1) * 8) * ALD +
                                           ((lane >> 3) & 1) * 16);
    const uint32_t voffV = sb + (uint32_t)((((lane >> 3) & 1) * 8 + (lane & 7)) * ALD +
                                           ((lane >> 4) & 1) * 16);

    float mstate[2] = { -1e30f, -1e30f };
    float lstate[2] = { 0.0f, 0.0f };
    float O[8][4];
#pragma unroll
    for (int j = 0; j < 8; j++)
#pragma unroll
        for (int t = 0; t < 4; t++) O[j][t] = 0.0f;

    const int row0 = q0 + wid * 16 + (lane >> 2);
    const int mcol = (lane & 3) * 2;
    const int* mrow0 = Mb + (size_t)row0 * S_;
    const int* mrow1 = Mb + (size_t)(row0 + 8) * S_;

    for (int k0 = 0; k0 < S_; k0 += ATK) {
        __syncthreads();
#pragma unroll
        for (int i = 0; i < 2; i++) {
            const int idx = tid + i * 256;
            const int rr = idx >> 3;
            const int cc = idx & 7;
            const size_t g = (size_t)(k0 + rr) * D_ + cc * 8;
            *(uint4*)(smem + AOFF_KH + rr * ALD + cc * 16) = *(const uint4*)&Khb[g];
            *(uint4*)(smem + AOFF_KL + rr * ALD + cc * 16) = *(const uint4*)&Klb[g];
            *(uint4*)(smem + AOFF_VH + rr * ALD + cc * 16) = *(const uint4*)&Vhb[g];
            *(uint4*)(smem + AOFF_VL + rr * ALD + cc * 16) = *(const uint4*)&Vlb[g];
        }
        __syncthreads();

        // ---- S = Q K^T (2-term) ----
        float Sf[8][4];
#pragma unroll
        for (int j = 0; j < 8; j++)
#pragma unroll
            for (int tt = 0; tt < 4; tt++) Sf[j][tt] = 0.0f;

#pragma unroll
        for (int kc = 0; kc < 4; kc++) {
            const uint32_t kb = (uint32_t)(kc * 32);
            uint32_t ah[4];
            ldsm4(ah, aoffQ + AOFF_QH + kb);
#pragma unroll
            for (int jp = 0; jp < 4; jp++) {
                uint32_t kh[4], kl[4];
                ldsm4(kh, boffK + AOFF_KH + (uint32_t)(jp * 16 * ALD) + kb);
                ldsm4(kl, boffK + AOFF_KL + (uint32_t)(jp * 16 * ALD) + kb);
                mma16816(Sf[jp * 2],     ah[0], ah[1], ah[2], ah[3], kh[0], kh[1]);
                mma16816(Sf[jp * 2],     ah[0], ah[1], ah[2], ah[3], kl[0], kl[1]);
                mma16816(Sf[jp * 2 + 1], ah[0], ah[1], ah[2], ah[3], kh[2], kh[3]);
                mma16816(Sf[jp * 2 + 1], ah[0], ah[1], ah[2], ah[3], kl[2], kl[3]);
            }
        }

        // ---- scale + mask ----
#pragma unroll
        for (int j = 0; j < 8; j++) {
            int2 mv0 = *(const int2*)&mrow0[k0 + j * 8 + mcol];
            int2 mv1 = *(const int2*)&mrow1[k0 + j * 8 + mcol];
            Sf[j][0] = (mv0.x == 0) ? -1e9f : Sf[j][0] * 0.125f;
            Sf[j][1] = (mv0.y == 0) ? -1e9f : Sf[j][1] * 0.125f;
            Sf[j][2] = (mv1.x == 0) ? -1e9f : Sf[j][2] * 0.125f;
            Sf[j][3] = (mv1.y == 0) ? -1e9f : Sf[j][3] * 0.125f;
        }

        // ---- online softmax ----
        float corr[2];
#pragma unroll
        for (int rr = 0; rr < 2; rr++) {
            float mx = -1e30f;
#pragma unroll
            for (int j = 0; j < 8; j++)
                mx = fmaxf(mx, fmaxf(Sf[j][rr * 2], Sf[j][rr * 2 + 1]));
            mx = fmaxf(mx, __shfl_xor_sync(0xFFFFFFFF, mx, 1));
            mx = fmaxf(mx, __shfl_xor_sync(0xFFFFFFFF, mx, 2));
            float mnew = fmaxf(mstate[rr], mx);
            corr[rr] = __expf(mstate[rr] - mnew);
            float sum = 0.0f;
#pragma unroll
            for (int j = 0; j < 8; j++) {
                float p0 = __expf(Sf[j][rr * 2]     - mnew);
                float p1 = __expf(Sf[j][rr * 2 + 1] - mnew);
                Sf[j][rr * 2] = p0; Sf[j][rr * 2 + 1] = p1;
                sum += p0 + p1;
            }
            sum += __shfl_xor_sync(0xFFFFFFFF, sum, 1);
            sum += __shfl_xor_sync(0xFFFFFFFF, sum, 2);
            lstate[rr] = lstate[rr] * corr[rr] + sum;
            mstate[rr] = mnew;
        }

#pragma unroll
        for (int j = 0; j < 8; j++) {
            O[j][0] *= corr[0]; O[j][1] *= corr[0];
            O[j][2] *= corr[1]; O[j][3] *= corr[1];
        }

        // ---- pack P hi ----
        uint32_t aPh[4][4];
#pragma unroll
        for (int kc = 0; kc < 4; kc++) {
#pragma unroll
            for (int half = 0; half < 2; half++) {
                const int j = kc * 2 + half;
#pragma unroll
                for (int rr = 0; rr < 2; rr++) {
                    __half2 hp = __halves2half2(__float2half_rn(Sf[j][rr * 2]),
                                                __float2half_rn(Sf[j][rr * 2 + 1]));
                    aPh[kc][half * 2 + rr] = *(uint32_t*)&hp;
                }
            }
        }

        // ---- O += P V (2-term) ----
#pragma unroll
        for (int kc = 0; kc < 4; kc++) {
#pragma unroll
            for (int jp = 0; jp < 4; jp++) {
                uint32_t vh[4], vl[4];
                ldsm4t(vh, voffV + AOFF_VH + (uint32_t)(kc * 16 * ALD) + (uint32_t)(jp * 32));
                ldsm4t(vl, voffV + AOFF_VL + (uint32_t)(kc * 16 * ALD) + (uint32_t)(jp * 32));
                mma16816(O[jp * 2],     aPh[kc][0], aPh[kc][1], aPh[kc][2], aPh[kc][3], vh[0], vh[1]);
                mma16816(O[jp * 2],     aPh[kc][0], aPh[kc][1], aPh[kc][2], aPh[kc][3], vl[0], vl[1]);
                mma16816(O[jp * 2 + 1], aPh[kc][0], aPh[kc][1], aPh[kc][2], aPh[kc][3], vh[2], vh[3]);
                mma16816(O[jp * 2 + 1], aPh[kc][0], aPh[kc][1], aPh[kc][2], aPh[kc][3], vl[2], vl[3]);
            }
        }
        __syncthreads();
    }

    // ---- finalize: write context hi only ----
    const float inv0 = 1.0f / lstate[0];
    const float inv1 = 1.0f / lstate[1];
    __half* Chb = Ch + base;
#pragma unroll
    for (int j = 0; j < 8; j++) {
        const int col = j * 8 + mcol;
        *(uint32_t*)&Chb[(size_t)row0 * D_ + col] =
            packh(O[j][0] * inv0, O[j][1] * inv0);
        *(uint32_t*)&Chb[(size_t)(row0 + 8) * D_ + col] =
            packh(O[j][2] * inv1, O[j][3] * inv1);
    }
}

// ---------------------------------------------------------------------------
// Launch
// ---------------------------------------------------------------------------
extern "C" void kernel_launch(void* const* d_in, const int* in_sizes, int n_in,
                              void* d_out, int out_size)
{
    (void)in_sizes; (void)n_in; (void)out_size;
    const float* q    = (const float*)d_in[0];
    const float* k    = (const float*)d_in[1];
    const float* v    = (const float*)d_in[2];
    const int*   mask = (const int*)d_in[3];
    const float* w_q  = (const float*)d_in[4];
    const float* b_q  = (const float*)d_in[5];
    const float* w_k  = (const float*)d_in[6];
    const float* b_k  = (const float*)d_in[7];
    const float* w_v  = (const float*)d_in[8];
    const float* b_v  = (const float*)d_in[9];
    const float* w_o  = (const float*)d_in[10];
    const float* b_o  = (const float*)d_in[11];
    float* out = (float*)d_out;

    __half *gQh, *gKh, *gKl, *gVh, *gVl, *gCh;
    cudaGetSymbolAddress((void**)&gQh, g_Qh);
    cudaGetSymbolAddress((void**)&gKh, g_Kh);
    cudaGetSymbolAddress((void**)&gKl, g_Kl);
    cudaGetSymbolAddress((void**)&gVh, g_Vh);
    cudaGetSymbolAddress((void**)&gVl, g_Vl);
    cudaGetSymbolAddress((void**)&gCh, g_Ch);

    cudaFuncSetAttribute(attn_mma_kernel,
                         cudaFuncAttributeMaxDynamicSharedMemorySize,
                         ATTN_SMEM_BYTES);

    dim3 gblk(256);

    // Q/K/V projections (2-term). Q needs hi only (Yl = nullptr -> skip lo writes).
    dim3 ggrid3(D_ / BN, M_ / BM, 3);
    gemm_mma_kernel<0><<<ggrid3, gblk>>>(
        q, k, v, nullptr,
        w_q, w_k, w_v, b_q, b_k, b_v,
        nullptr,
        gQh, gKh, gVh, nullptr, gKl, gVl);

    dim3 ablk(256);
    dim3 agrid(S_ / ATQ, B_ * H_);    // (16, 32)
    attn_mma_kernel<<<agrid, ablk, ATTN_SMEM_BYTES>>>(
        gQh, gKh, gKl, gVh, gVl, mask, gCh);

    // final projection (2-term, A = Ch)
    dim3 ggrid1(D_ / BN, M_ / BM, 1);
    gemm_mma_kernel<1><<<ggrid1, gblk>>>(
        nullptr, nullptr, nullptr, gCh,
        w_o, nullptr, nullptr, b_o, nullptr, nullptr,
        out,
        nullptr, nullptr, nullptr, nullptr, nullptr, nullptr);
}